// round 1
// baseline (speedup 1.0000x reference)
#include <cuda_runtime.h>
#include <cuda_bf16.h>

// PartialMatchingLoss: mean over all partial points of min Euclidean distance
// to completed points (per batch). B=8, M=4096 (partial), N=8192 (completed), D=3.
//
// d^2 = ||p||^2 + (||c||^2 - 2 p.c). ||p||^2 is constant per query, so
// min_n d^2 = ||p||^2 + min_n (||c||^2 - 2 p.c). Inner loop: 3 FFMA + 1 FMNMX.

#define B_ 8
#define M_ 4096
#define N_ 8192

#define NSPLIT 4
#define NTILE (N_ / NSPLIT)          // 2048 completed points per CTA tile
#define K1_THREADS 256
#define PPT 2                         // partial (query) points per thread
#define MCHUNK (K1_THREADS * PPT)     // 512 queries per CTA
#define NMCHUNK (M_ / MCHUNK)         // 8
#define K1_GRID (B_ * NMCHUNK * NSPLIT) // 256 CTAs

#define TOTAL_P (B_ * M_)             // 32768
#define K2_THREADS 256
#define K2_GRID (TOTAL_P / K2_THREADS) // 128

// Scratch: every slot is written unconditionally each launch -> no init needed,
// fully deterministic (no atomics anywhere).
__device__ float g_minbuf[NSPLIT][TOTAL_P];
__device__ float g_blocksum[K2_GRID];

__global__ void __launch_bounds__(K1_THREADS)
k1_min_tile(const float* __restrict__ completed, const float* __restrict__ partial) {
    __shared__ float4 sc[NTILE];   // 32 KB: {x, y, z, ||c||^2}

    const int bid = blockIdx.x;
    const int ns  = bid & (NSPLIT - 1);
    const int r   = bid >> 2;
    const int mc  = r & (NMCHUNK - 1);
    const int b   = r >> 3;
    const int tid = threadIdx.x;

    // Stage this CTA's completed tile into shared memory with precomputed ||c||^2.
    const float* cg = completed + ((size_t)b * N_ + (size_t)ns * NTILE) * 3;
    for (int i = tid; i < NTILE; i += K1_THREADS) {
        float x = cg[3 * i + 0];
        float y = cg[3 * i + 1];
        float z = cg[3 * i + 2];
        sc[i] = make_float4(x, y, z, fmaf(x, x, fmaf(y, y, z * z)));
    }
    __syncthreads();

    // Load PPT query points per thread; keep -2*p in registers.
    const int m0 = mc * MCHUNK;
    float m2x[PPT], m2y[PPT], m2z[PPT], mn[PPT];
#pragma unroll
    for (int t = 0; t < PPT; t++) {
        int m = m0 + tid + t * K1_THREADS;  // coalesced across the warp
        const float* pg = partial + ((size_t)b * M_ + m) * 3;
        m2x[t] = -2.0f * pg[0];
        m2y[t] = -2.0f * pg[1];
        m2z[t] = -2.0f * pg[2];
        mn[t]  = 3.4e38f;
    }

    // Hot loop: per completed point, per query: 3 FFMA (fma pipe) + 1 FMNMX (alu pipe).
    // All lanes read the same smem address -> broadcast, conflict-free.
#pragma unroll 8
    for (int j = 0; j < NTILE; j++) {
        float4 c = sc[j];
#pragma unroll
        for (int t = 0; t < PPT; t++) {
            float s = fmaf(m2x[t], c.x, fmaf(m2y[t], c.y, fmaf(m2z[t], c.z, c.w)));
            mn[t] = fminf(mn[t], s);
        }
    }

#pragma unroll
    for (int t = 0; t < PPT; t++) {
        g_minbuf[ns][b * M_ + m0 + tid + t * K1_THREADS] = mn[t];
    }
}

__global__ void __launch_bounds__(K2_THREADS)
k2_reduce(const float* __restrict__ partial) {
    __shared__ float ssum[K2_THREADS];
    const int pid = blockIdx.x * K2_THREADS + threadIdx.x;  // pid = b*M + m

    float s = g_minbuf[0][pid];
#pragma unroll
    for (int k = 1; k < NSPLIT; k++) s = fminf(s, g_minbuf[k][pid]);

    const float* pg = partial + (size_t)pid * 3;
    float psq = fmaf(pg[0], pg[0], fmaf(pg[1], pg[1], pg[2] * pg[2]));
    float d2  = psq + s;
    float d   = sqrtf(fmaxf(d2, 0.0f));

    ssum[threadIdx.x] = d;
    __syncthreads();
#pragma unroll
    for (int off = K2_THREADS / 2; off > 0; off >>= 1) {
        if (threadIdx.x < off) ssum[threadIdx.x] += ssum[threadIdx.x + off];
        __syncthreads();
    }
    if (threadIdx.x == 0) g_blocksum[blockIdx.x] = ssum[0];
}

__global__ void k3_final(float* __restrict__ out) {
    __shared__ float ssum[K2_GRID];
    ssum[threadIdx.x] = g_blocksum[threadIdx.x];
    __syncthreads();
#pragma unroll
    for (int off = K2_GRID / 2; off > 0; off >>= 1) {
        if (threadIdx.x < off) ssum[threadIdx.x] += ssum[threadIdx.x + off];
        __syncthreads();
    }
    if (threadIdx.x == 0) out[0] = ssum[0] * (1.0f / (float)TOTAL_P);
}

extern "C" void kernel_launch(void* const* d_in, const int* in_sizes, int n_in,
                              void* d_out, int out_size) {
    const float* completed = (const float*)d_in[0];  // (8, 8192, 3)
    const float* partial   = (const float*)d_in[1];  // (8, 4096, 3)
    // Defensive: if metadata order is swapped, detect by element counts.
    if (n_in >= 2 && in_sizes[0] == B_ * M_ * 3 && in_sizes[1] == B_ * N_ * 3) {
        completed = (const float*)d_in[1];
        partial   = (const float*)d_in[0];
    }

    k1_min_tile<<<K1_GRID, K1_THREADS>>>(completed, partial);
    k2_reduce<<<K2_GRID, K2_THREADS>>>(partial);
    k3_final<<<1, K2_GRID>>>((float*)d_out);
}

// round 2
// speedup vs baseline: 1.1245x; 1.1245x over previous
#include <cuda_runtime.h>
#include <cuda_bf16.h>

// PartialMatchingLoss: mean over partial points of min Euclidean distance to
// completed points (per batch). B=8, M=4096, N=8192, D=3.
//
// min_n d^2 = ||p||^2 + min_n (||c||^2 - 2 p.c).
// Hot loop uses sm_103a packed fma.rn.f32x2: smem tile stores each completed
// point duplicated as {x,x},{y,y},{z,z},{c2,c2} so one LDS.128 feeds a packed
// FMA directly; 2 queries ride in each packed register.

#define B_ 8
#define M_ 4096
#define N_ 8192

#define THREADS 256
#define PPT 4                       // queries per thread
#define QP  (PPT / 2)               // packed query pairs = 2
#define MCHUNK (THREADS * PPT)      // 1024 queries per CTA
#define NMCHUNK (M_ / MCHUNK)       // 4
#define NSPLIT 32
#define NTILE (N_ / NSPLIT)         // 256 completed points per tile
#define K1_GRID (B_ * NMCHUNK * NSPLIT) // 1024 CTAs

#define TOTAL_P (B_ * M_)           // 32768
#define K2_THREADS 256
#define K2_GRID (TOTAL_P / K2_THREADS) // 128

// Scratch (no allocation allowed): every slot written unconditionally each
// launch, no atomics -> deterministic.
__device__ float g_minbuf[NSPLIT][TOTAL_P];   // 4 MB
__device__ float g_blocksum[K2_GRID];

#define FMA_F32X2(d, a, b, c) \
    asm("fma.rn.f32x2 %0, %1, %2, %3;" : "=l"(d) : "l"(a), "l"(b), "l"(c))

__device__ __forceinline__ unsigned long long pk2(float a, float b) {
    unsigned long long r;
    asm("mov.b64 %0, {%1, %2};" : "=l"(r) : "f"(a), "f"(b));
    return r;
}
__device__ __forceinline__ void unpk2(float& lo, float& hi, unsigned long long v) {
    asm("mov.b64 {%0, %1}, %2;" : "=f"(lo), "=f"(hi) : "l"(v));
}

__global__ void __launch_bounds__(THREADS)
k1_min_tile(const float* __restrict__ completed, const float* __restrict__ partial) {
    // Per point: {x,x},{y,y} in sc[2j], {z,z},{c2,c2} in sc[2j+1]  (32 B)
    __shared__ ulonglong2 sc[NTILE * 2];   // 8 KB

    const int bid = blockIdx.x;
    const int ns  = bid & (NSPLIT - 1);
    const int r   = bid >> 5;
    const int mc  = r & (NMCHUNK - 1);
    const int b   = r >> 2;
    const int tid = threadIdx.x;

    // Stage tile with precomputed ||c||^2, duplicated for packed math.
    const float* cg = completed + ((size_t)b * N_ + (size_t)ns * NTILE) * 3;
    for (int i = tid; i < NTILE; i += THREADS) {
        float x = cg[3 * i + 0];
        float y = cg[3 * i + 1];
        float z = cg[3 * i + 2];
        float w = fmaf(x, x, fmaf(y, y, z * z));
        sc[2 * i + 0] = make_ulonglong2(pk2(x, x), pk2(y, y));
        sc[2 * i + 1] = make_ulonglong2(pk2(z, z), pk2(w, w));
    }
    __syncthreads();

    // Pack -2*p for query pairs (t=2p, 2p+1), coalesced global reads.
    const int m0 = mc * MCHUNK;
    unsigned long long qx[QP], qy[QP], qz[QP];
    float mn[PPT];
#pragma unroll
    for (int p = 0; p < QP; p++) {
        int ma = m0 + tid + (2 * p + 0) * THREADS;
        int mb = m0 + tid + (2 * p + 1) * THREADS;
        const float* pa = partial + ((size_t)b * M_ + ma) * 3;
        const float* pb = partial + ((size_t)b * M_ + mb) * 3;
        qx[p] = pk2(-2.0f * pa[0], -2.0f * pb[0]);
        qy[p] = pk2(-2.0f * pa[1], -2.0f * pb[1]);
        qz[p] = pk2(-2.0f * pa[2], -2.0f * pb[2]);
        mn[2 * p + 0] = 3.4e38f;
        mn[2 * p + 1] = 3.4e38f;
    }

    // Hot loop: 2 LDS.128 + 6 FFMA2 + 4 FMNMX per completed point (4 pairs).
#pragma unroll 4
    for (int j = 0; j < NTILE; j++) {
        ulonglong2 A = sc[2 * j + 0];   // {xx, yy}
        ulonglong2 Bv = sc[2 * j + 1];  // {zz, ww}
#pragma unroll
        for (int p = 0; p < QP; p++) {
            unsigned long long acc;
            FMA_F32X2(acc, qz[p], Bv.x, Bv.y);
            FMA_F32X2(acc, qy[p], A.y, acc);
            FMA_F32X2(acc, qx[p], A.x, acc);
            float lo, hi;
            unpk2(lo, hi, acc);
            mn[2 * p + 0] = fminf(mn[2 * p + 0], lo);
            mn[2 * p + 1] = fminf(mn[2 * p + 1], hi);
        }
    }

#pragma unroll
    for (int t = 0; t < PPT; t++) {
        g_minbuf[ns][b * M_ + m0 + tid + t * THREADS] = mn[t];
    }
}

__global__ void __launch_bounds__(K2_THREADS)
k2_reduce(const float* __restrict__ partial) {
    __shared__ float ssum[K2_THREADS];
    const int pid = blockIdx.x * K2_THREADS + threadIdx.x;  // pid = b*M + m

    float s = g_minbuf[0][pid];
#pragma unroll
    for (int k = 1; k < NSPLIT; k++) s = fminf(s, g_minbuf[k][pid]);

    const float* pg = partial + (size_t)pid * 3;
    float psq = fmaf(pg[0], pg[0], fmaf(pg[1], pg[1], pg[2] * pg[2]));
    float d   = sqrtf(fmaxf(psq + s, 0.0f));

    ssum[threadIdx.x] = d;
    __syncthreads();
#pragma unroll
    for (int off = K2_THREADS / 2; off > 0; off >>= 1) {
        if (threadIdx.x < off) ssum[threadIdx.x] += ssum[threadIdx.x + off];
        __syncthreads();
    }
    if (threadIdx.x == 0) g_blocksum[blockIdx.x] = ssum[0];
}

__global__ void k3_final(float* __restrict__ out) {
    __shared__ float ssum[K2_GRID];
    ssum[threadIdx.x] = g_blocksum[threadIdx.x];
    __syncthreads();
#pragma unroll
    for (int off = K2_GRID / 2; off > 0; off >>= 1) {
        if (threadIdx.x < off) ssum[threadIdx.x] += ssum[threadIdx.x + off];
        __syncthreads();
    }
    if (threadIdx.x == 0) out[0] = ssum[0] * (1.0f / (float)TOTAL_P);
}

extern "C" void kernel_launch(void* const* d_in, const int* in_sizes, int n_in,
                              void* d_out, int out_size) {
    const float* completed = (const float*)d_in[0];  // (8, 8192, 3)
    const float* partial   = (const float*)d_in[1];  // (8, 4096, 3)
    if (n_in >= 2 && in_sizes[0] == B_ * M_ * 3 && in_sizes[1] == B_ * N_ * 3) {
        completed = (const float*)d_in[1];
        partial   = (const float*)d_in[0];
    }

    k1_min_tile<<<K1_GRID, THREADS>>>(completed, partial);
    k2_reduce<<<K2_GRID, K2_THREADS>>>(partial);
    k3_final<<<1, K2_GRID>>>((float*)d_out);
}

// round 6
// speedup vs baseline: 1.3464x; 1.1973x over previous
#include <cuda_runtime.h>
#include <cuda_bf16.h>

// PartialMatchingLoss: mean over partial points of min Euclidean distance to
// completed points (per batch). B=8, M=4096, N=8192, D=3.
//
// min_n d^2 = ||p||^2 + min_n (||c||^2 - 2 p.c).
// Packed axis = completed points: smem holds {x_2j,x_2j+1},{y,y'},{z,z'},{w,w'}
// (16 B/point, no duplication). Queries are duplicated into packed registers
// once (free). Inner loop per 2 completed points per query:
//   3 x fma.rn.f32x2 (fma pipe) + 2 x FMNMX on the halves (alu pipe).

#define B_ 8
#define M_ 4096
#define N_ 8192

#define THREADS 128
#define Q 8                          // queries per thread
#define MCHUNK (THREADS * Q)         // 1024 queries per CTA
#define NMCHUNK (M_ / MCHUNK)        // 4
#define NSPLIT 32
#define NTILE (N_ / NSPLIT)          // 256 completed points per tile
#define NGROUP (NTILE / 2)           // 128 packed point-pairs
#define K1_GRID (B_ * NMCHUNK * NSPLIT) // 1024 CTAs

#define TOTAL_P (B_ * M_)            // 32768
#define K2_THREADS 256
#define K2_GRID (TOTAL_P / K2_THREADS) // 128

// Scratch (no allocation allowed): every slot written unconditionally each
// launch, no atomics -> deterministic.
__device__ float g_minbuf[NSPLIT][TOTAL_P];   // 4 MB
__device__ float g_blocksum[K2_GRID];

#define FMA_F32X2(d, a, b, c) \
    asm("fma.rn.f32x2 %0, %1, %2, %3;" : "=l"(d) : "l"(a), "l"(b), "l"(c))

__device__ __forceinline__ unsigned long long pk2(float a, float b) {
    unsigned long long r;
    asm("mov.b64 %0, {%1, %2};" : "=l"(r) : "f"(a), "f"(b));
    return r;
}
__device__ __forceinline__ void unpk2(float& lo, float& hi, unsigned long long v) {
    asm("mov.b64 {%0, %1}, %2;" : "=f"(lo), "=f"(hi) : "l"(v));
}

__global__ void __launch_bounds__(THREADS, 5)
k1_min_tile(const float* __restrict__ completed, const float* __restrict__ partial) {
    // Group g (points 2g, 2g+1):
    //   sxy[g] = { {x,x'}, {y,y'} },  szw[g] = { {z,z'}, {w,w'} }   (w = ||c||^2)
    __shared__ ulonglong2 sxy[NGROUP];   // 2 KB
    __shared__ ulonglong2 szw[NGROUP];   // 2 KB

    const int bid = blockIdx.x;
    const int ns  = bid & (NSPLIT - 1);
    const int r   = bid >> 5;
    const int mc  = r & (NMCHUNK - 1);
    const int b   = r >> 2;
    const int tid = threadIdx.x;

    // Stage tile: thread g packs point-pair g.  NGROUP == THREADS -> 1 pass.
    {
        const float* cg = completed + ((size_t)b * N_ + (size_t)ns * NTILE + 2 * tid) * 3;
        float x0 = cg[0], y0 = cg[1], z0 = cg[2];
        float x1 = cg[3], y1 = cg[4], z1 = cg[5];
        float w0 = fmaf(x0, x0, fmaf(y0, y0, z0 * z0));
        float w1 = fmaf(x1, x1, fmaf(y1, y1, z1 * z1));
        sxy[tid] = make_ulonglong2(pk2(x0, x1), pk2(y0, y1));
        szw[tid] = make_ulonglong2(pk2(z0, z1), pk2(w0, w1));
    }

    // Queries: -2*p duplicated into packed registers (free duplication).
    const int m0 = mc * MCHUNK;
    unsigned long long qx[Q], qy[Q], qz[Q];
    float mnE[Q], mnO[Q];
#pragma unroll
    for (int t = 0; t < Q; t++) {
        const float* pg = partial + ((size_t)b * M_ + m0 + tid + t * THREADS) * 3;
        float vx = -2.0f * pg[0], vy = -2.0f * pg[1], vz = -2.0f * pg[2];
        qx[t] = pk2(vx, vx);
        qy[t] = pk2(vy, vy);
        qz[t] = pk2(vz, vz);
        mnE[t] = 3.4e38f;
        mnO[t] = 3.4e38f;
    }
    __syncthreads();

    // Hot loop: per group (2 points): 2 LDS.128 + Q*(3 FFMA2 + 2 FMNMX).
    // All lanes read the same smem address -> broadcast, conflict-free.
#pragma unroll 4
    for (int g = 0; g < NGROUP; g++) {
        ulonglong2 A = sxy[g];   // {xx', yy'}
        ulonglong2 Bv = szw[g];  // {zz', ww'}
#pragma unroll
        for (int t = 0; t < Q; t++) {
            unsigned long long acc;
            FMA_F32X2(acc, qz[t], Bv.x, Bv.y);
            FMA_F32X2(acc, qy[t], A.y, acc);
            FMA_F32X2(acc, qx[t], A.x, acc);
            float lo, hi;
            unpk2(lo, hi, acc);
            mnE[t] = fminf(mnE[t], lo);   // even-point chain
            mnO[t] = fminf(mnO[t], hi);   // odd-point chain (independent)
        }
    }

#pragma unroll
    for (int t = 0; t < Q; t++) {
        g_minbuf[ns][b * M_ + m0 + tid + t * THREADS] = fminf(mnE[t], mnO[t]);
    }
}

__global__ void __launch_bounds__(K2_THREADS)
k2_reduce(const float* __restrict__ partial) {
    __shared__ float ssum[K2_THREADS];
    const int pid = blockIdx.x * K2_THREADS + threadIdx.x;  // pid = b*M + m

    float s = g_minbuf[0][pid];
#pragma unroll
    for (int k = 1; k < NSPLIT; k++) s = fminf(s, g_minbuf[k][pid]);

    const float* pg = partial + (size_t)pid * 3;
    float psq = fmaf(pg[0], pg[0], fmaf(pg[1], pg[1], pg[2] * pg[2]));
    float d   = sqrtf(fmaxf(psq + s, 0.0f));

    ssum[threadIdx.x] = d;
    __syncthreads();
#pragma unroll
    for (int off = K2_THREADS / 2; off > 0; off >>= 1) {
        if (threadIdx.x < off) ssum[threadIdx.x] += ssum[threadIdx.x + off];
        __syncthreads();
    }
    if (threadIdx.x == 0) g_blocksum[blockIdx.x] = ssum[0];
}

__global__ void k3_final(float* __restrict__ out) {
    __shared__ float ssum[K2_GRID];
    ssum[threadIdx.x] = g_blocksum[threadIdx.x];
    __syncthreads();
#pragma unroll
    for (int off = K2_GRID / 2; off > 0; off >>= 1) {
        if (threadIdx.x < off) ssum[threadIdx.x] += ssum[threadIdx.x + off];
        __syncthreads();
    }
    if (threadIdx.x == 0) out[0] = ssum[0] * (1.0f / (float)TOTAL_P);
}

extern "C" void kernel_launch(void* const* d_in, const int* in_sizes, int n_in,
                              void* d_out, int out_size) {
    const float* completed = (const float*)d_in[0];  // (8, 8192, 3)
    const float* partial   = (const float*)d_in[1];  // (8, 4096, 3)
    if (n_in >= 2 && in_sizes[0] == B_ * M_ * 3 && in_sizes[1] == B_ * N_ * 3) {
        completed = (const float*)d_in[1];
        partial   = (const float*)d_in[0];
    }

    k1_min_tile<<<K1_GRID, THREADS>>>(completed, partial);
    k2_reduce<<<K2_GRID, K2_THREADS>>>(partial);
    k3_final<<<1, K2_GRID>>>((float*)d_out);
}